// round 5
// baseline (speedup 1.0000x reference)
#include <cuda_runtime.h>
#include <cstdint>

// ---------------------------------------------------------------------------
// SphericalExpansion, round 5: ZERO shuffles. Lane L owns segment floats
// {L, L+32, L+64, L+96} (same lm = L&15, n = h+2k, h = L>>4) and computes
// its 4 radial basis values directly (4x EX2 on the idle MUFU pipe) from
// 4 preloaded per-lane centers. MIO pipe carries only loads + 4 REDs/edge.
// ---------------------------------------------------------------------------

__constant__ float cA[16][4] = {   // f1 = a0 + ax*x + ay*y + az*z (one-hot)
    {1,0,0,0}, {0,0,1,0}, {0,0,0,1}, {0,1,0,0},
    {1,0,0,0}, {1,0,0,0}, {1,0,0,0}, {1,0,0,0},
    {1,0,0,0}, {0,0,1,0}, {0,1,0,0}, {0,0,1,0},
    {0,0,0,1}, {0,1,0,0}, {0,0,0,1}, {0,1,0,0},
};

__constant__ float cF[16][7] = {   // f2 = c0+cx*x2+cy*y2+cz*z2+cxy*xy+cyz*yz+czx*zx
    {0.28209479177387814f, 0,0,0, 0,0,0},
    {0.4886025119029199f,  0,0,0, 0,0,0},
    {0.4886025119029199f,  0,0,0, 0,0,0},
    {0.4886025119029199f,  0,0,0, 0,0,0},
    {0, 0,0,0, 1.0925484305920792f,0,0},
    {0, 0,0,0, 0,1.0925484305920792f,0},
    {0,-0.31539156525252005f,-0.31539156525252005f,0.6307831305050401f, 0,0,0},
    {0, 0,0,0, 0,0,1.0925484305920792f},
    {0, 0.5462742152960396f,-0.5462742152960396f,0, 0,0,0},
    {0, 1.7701307697799304f,-0.5900435899266435f,0, 0,0,0},
    {0, 0,0,0, 0,2.890611442640554f,0},
    {0,-0.4570457994644658f,-0.4570457994644658f,1.8281831978578632f, 0,0,0},
    {0,-1.1195289977703462f,-1.1195289977703462f,0.7463526651802308f, 0,0,0},
    {0,-0.4570457994644658f,-0.4570457994644658f,1.8281831978578632f, 0,0,0},
    {0, 1.445305721320277f,-1.445305721320277f,0, 0,0,0},
    {0, 0.5900435899266435f,-1.7701307697799304f,0, 0,0,0},
};

__constant__ int cLM2L[16] = {0,1,1,1, 2,2,2,2, 2,3,3,3, 3,3,3,3};

// -2 * log2(e): exp(-2 t^2) = exp2(K2E * t^2)
#define K2E (-2.8853900817779268f)

__global__ void __launch_bounds__(256) zero_out_kernel(float4* out, int n4) {
    int i = blockIdx.x * blockDim.x + threadIdx.x;
    int stride = gridDim.x * blockDim.x;
    float4 zv = make_float4(0.f, 0.f, 0.f, 0.f);
    for (; i < n4; i += stride) out[i] = zv;
}

__device__ __forceinline__ void red_f32(float* p, float v) {
    asm volatile("red.global.add.f32 [%0], %1;" :: "l"(p), "f"(v) : "memory");
}

__global__ void __launch_bounds__(256, 5) sph_expand_kernel(
    const float* __restrict__ dist,
    const float* __restrict__ dirs,      // [J,3]
    const float* __restrict__ centers,   // [32]
    const int*   __restrict__ zspec,     // [N_ATOMS]
    const int*   __restrict__ idx_i,     // [J]
    const int*   __restrict__ idx_j,     // [J]
    float*       __restrict__ out,       // [N_ATOMS*4*8*16]
    int J)
{
    const int lane  = threadIdx.x & 31;
    const int warp  = (blockIdx.x * blockDim.x + threadIdx.x) >> 5;
    const int nwarp = (gridDim.x * blockDim.x) >> 5;

    const int lm = lane & 15;
    const int h  = lane >> 4;            // parity of owned n
    const int l  = cLM2L[lm];
    const int cb = 8 * l + h;            // centers index base for this lane

    // 4 per-lane radial centers (n = h, h+2, h+4, h+6 of the same l)
    const float cen0 = centers[cb + 0];
    const float cen1 = centers[cb + 2];
    const float cen2 = centers[cb + 4];
    const float cen3 = centers[cb + 6];

    // Ylm coefficient tables
    const float a0 = cA[lm][0], ax = cA[lm][1], ay = cA[lm][2], az = cA[lm][3];
    const float f0 = cF[lm][0], fx = cF[lm][1], fy = cF[lm][2], fz = cF[lm][3];
    const float fxy = cF[lm][4], fyz = cF[lm][5], fzx = cF[lm][6];

    float* const outLane = out + lane;

    const int npacks = J >> 2;
    const float4* __restrict__ dist4 = (const float4*)dist;
    const float4* __restrict__ dirs4 = (const float4*)dirs;
    const int4*   __restrict__ ii4p  = (const int4*)idx_i;
    const int4*   __restrict__ jj4p  = (const int4*)idx_j;

    for (int pk = warp; pk < npacks; pk += nwarp) {
        // ---- batch loads: 4 edges, 10 LDGs ----
        const float4 r4 = __ldg(dist4 + pk);
        const float4 d0 = __ldg(dirs4 + 3*pk + 0);
        const float4 d1 = __ldg(dirs4 + 3*pk + 1);
        const float4 d2 = __ldg(dirs4 + 3*pk + 2);
        const int4   i4 = __ldg(ii4p + pk);
        const int4   j4 = __ldg(jj4p + pk);

        const int z0 = __ldg(zspec + j4.x);
        const int z1 = __ldg(zspec + j4.y);
        const int z2 = __ldg(zspec + j4.z);
        const int z3 = __ldg(zspec + j4.w);

        const float rr[4]  = {r4.x, r4.y, r4.z, r4.w};
        const float xx[4]  = {d0.x, d0.w, d1.z, d2.y};
        const float yy[4]  = {d0.y, d1.x, d1.w, d2.z};
        const float zzv[4] = {d0.z, d1.y, d2.x, d2.w};
        const int  seg[4]  = {(i4.x<<2)+z0, (i4.y<<2)+z1, (i4.z<<2)+z2, (i4.w<<2)+z3};

        #pragma unroll
        for (int k = 0; k < 4; k++) {
            const float r = rr[k], x = xx[k], y = yy[k], zz = zzv[k];

            // branchless shifted-cosine cutoff (rc=5, w=0.5)
            const float u  = __saturatef((r - 4.5f) * 2.0f);
            const float fc = 0.5f + 0.5f * cospif(u);

            // Y[lm] for this lane, cutoff folded in once
            const float x2 = x*x, y2 = y*y, z2 = zz*zz;
            const float xy = x*y, yz = y*zz, zx = zz*x;
            const float f1 = a0 + ax*x + ay*y + az*zz;
            const float f2 = f0 + fx*x2 + fy*y2 + fz*z2 + fxy*xy + fyz*yz + fzx*zx;
            const float Y  = f1 * f2 * fc;

            // 4 radial basis values, computed directly (no shuffles):
            // rb = exp(-2 t^2) = exp2(K2E * t^2)
            const float t0 = r - cen0, t1 = r - cen1, t2 = r - cen2, t3 = r - cen3;
            const float rb0 = exp2f(K2E * t0 * t0);
            const float rb1 = exp2f(K2E * t1 * t1);
            const float rb2 = exp2f(K2E * t2 * t2);
            const float rb3 = exp2f(K2E * t3 * t3);

            float* p = outLane + ((size_t)seg[k] << 7);
            red_f32(p,      Y * rb0);
            red_f32(p + 32, Y * rb1);
            red_f32(p + 64, Y * rb2);
            red_f32(p + 96, Y * rb3);
        }
    }

    // tail (J not a multiple of 4)
    for (int e = (npacks << 2) + warp; e < J; e += nwarp) {
        const float r  = __ldg(dist + e);
        const float x  = __ldg(dirs + 3*e + 0);
        const float y  = __ldg(dirs + 3*e + 1);
        const float zz = __ldg(dirs + 3*e + 2);
        const int   ii = __ldg(idx_i + e);
        const int   zj = __ldg(zspec + __ldg(idx_j + e));

        const float u  = __saturatef((r - 4.5f) * 2.0f);
        const float fc = 0.5f + 0.5f * cospif(u);

        const float x2 = x*x, y2 = y*y, z2 = zz*zz;
        const float xy = x*y, yz = y*zz, zx = zz*x;
        const float f1 = a0 + ax*x + ay*y + az*zz;
        const float f2 = f0 + fx*x2 + fy*y2 + fz*z2 + fxy*xy + fyz*yz + fzx*zx;
        const float Y  = f1 * f2 * fc;

        const float t0 = r - cen0, t1 = r - cen1, t2 = r - cen2, t3 = r - cen3;
        const float rb0 = exp2f(K2E * t0 * t0);
        const float rb1 = exp2f(K2E * t1 * t1);
        const float rb2 = exp2f(K2E * t2 * t2);
        const float rb3 = exp2f(K2E * t3 * t3);

        float* p = outLane + ((size_t)((ii << 2) + zj) << 7);
        red_f32(p,      Y * rb0);
        red_f32(p + 32, Y * rb1);
        red_f32(p + 64, Y * rb2);
        red_f32(p + 96, Y * rb3);
    }
}

extern "C" void kernel_launch(void* const* d_in, const int* in_sizes, int n_in,
                              void* d_out, int out_size) {
    const float* dist    = (const float*)d_in[0];
    const float* dirs    = (const float*)d_in[1];
    const float* centers = (const float*)d_in[2];
    const int*   zspec   = (const int*)d_in[3];
    const int*   idx_i   = (const int*)d_in[4];
    const int*   idx_j   = (const int*)d_in[5];
    float*       out     = (float*)d_out;
    const int J = in_sizes[0];

    const int n4 = out_size / 4;
    zero_out_kernel<<<1184, 256>>>((float4*)d_out, n4);

    const int blocks = 148 * 5;
    sph_expand_kernel<<<blocks, 256>>>(dist, dirs, centers, zspec,
                                       idx_i, idx_j, out, J);
}